// round 1
// baseline (speedup 1.0000x reference)
#include <cuda_runtime.h>
#include <math.h>

#define NB 16
#define ND 256
#define NHW 4096   // 64*64

// Scratch (static device arrays — allocation-free per harness rules)
__device__ float g_q [NB*ND*NHW];
__device__ float g_k [NB*ND*NHW];
__device__ float g_v [NB*ND*NHW];
__device__ float g_ao[NB*ND*NHW];          // score partials, then attention output
__device__ float g_scores[NB*64*64];
__device__ float g_attn  [NB*64*64];

// ---------------------------------------------------------------------------
// Kernel 1: fused QKV 1x1-conv GEMM.  Per (batch, proj): Out = W[256x256] @ X[256x4096] + bias
// grid (32 n-tiles, 2 m-tiles, 16*3), block 256, tile 128x128, k-chunk 8, 8x8 micro-tile
// ---------------------------------------------------------------------------
__global__ void __launch_bounds__(256) qkv_kernel(
    const float* __restrict__ x,
    const float* __restrict__ wq, const float* __restrict__ bq,
    const float* __restrict__ wk, const float* __restrict__ bk,
    const float* __restrict__ wv, const float* __restrict__ bv)
{
    const int proj = blockIdx.z % 3;
    const int b    = blockIdx.z / 3;
    const float* Wm   = (proj == 0) ? wq : (proj == 1) ? wk : wv;
    const float* bias = (proj == 0) ? bq : (proj == 1) ? bk : bv;
    float*       outp = (proj == 0) ? g_q : (proj == 1) ? g_k : g_v;

    const int nBase = blockIdx.x * 128;
    const int mBase = blockIdx.y * 128;
    const int tid = threadIdx.x;
    const int tx = tid & 15, ty = tid >> 4;

    __shared__ float As[8][128];   // [k][m]
    __shared__ float Bs[8][128];   // [k][n]

    float acc[8][8];
    #pragma unroll
    for (int i = 0; i < 8; i++)
        #pragma unroll
        for (int j = 0; j < 8; j++) acc[i][j] = 0.f;

    const float* xb = x + b * (ND * NHW);
    const int am  = tid >> 1;
    const int ak  = (tid & 1) * 4;
    const int bkr = tid >> 5;
    const int bn  = (tid & 31) * 4;

    for (int kk = 0; kk < ND; kk += 8) {
        float4 a   = *(const float4*)(Wm + (mBase + am) * ND + kk + ak);
        float4 bv4 = *(const float4*)(xb + (kk + bkr) * NHW + nBase + bn);
        As[ak + 0][am] = a.x; As[ak + 1][am] = a.y;
        As[ak + 2][am] = a.z; As[ak + 3][am] = a.w;
        *(float4*)&Bs[bkr][bn] = bv4;
        __syncthreads();
        #pragma unroll
        for (int k = 0; k < 8; k++) {
            float4 a0 = *(float4*)&As[k][ty * 4];
            float4 a1 = *(float4*)&As[k][64 + ty * 4];
            float4 b0 = *(float4*)&Bs[k][tx * 4];
            float4 b1 = *(float4*)&Bs[k][64 + tx * 4];
            float av[8] = {a0.x, a0.y, a0.z, a0.w, a1.x, a1.y, a1.z, a1.w};
            float bw[8] = {b0.x, b0.y, b0.z, b0.w, b1.x, b1.y, b1.z, b1.w};
            #pragma unroll
            for (int i = 0; i < 8; i++)
                #pragma unroll
                for (int j = 0; j < 8; j++) acc[i][j] += av[i] * bw[j];
        }
        __syncthreads();
    }

    #pragma unroll
    for (int i = 0; i < 8; i++) {
        const int m = (i < 4) ? (ty * 4 + i) : (64 + ty * 4 + i - 4);
        const int c = mBase + m;
        const float bb = bias[c];
        float* op = outp + (b * ND + c) * NHW + nBase;
        float4 r0 = make_float4(acc[i][0] + bb, acc[i][1] + bb, acc[i][2] + bb, acc[i][3] + bb);
        float4 r1 = make_float4(acc[i][4] + bb, acc[i][5] + bb, acc[i][6] + bb, acc[i][7] + bb);
        *(float4*)(op + tx * 4)      = r0;
        *(float4*)(op + 64 + tx * 4) = r1;
    }
}

// ---------------------------------------------------------------------------
// Kernel 2: per-channel score partials.
// Token t=(i2,i4): pixel (i2*8+i3, i4*8+i5); e=(d,i3,i5).
// Block (d, b): partial[t][u] = sum_{i3,i5} Q[t][l] * K[u][l]  -> g_ao[(b*256+d)*4096 + t*64+u]
// ---------------------------------------------------------------------------
__global__ void __launch_bounds__(256) scores_partial_kernel()
{
    const int d = blockIdx.x;
    const int b = blockIdx.y;
    const int tid = threadIdx.x;
    __shared__ float Qs[64][65];   // [l][t]
    __shared__ float Ks[64][65];
    const float* qb = g_q + (b * ND + d) * NHW;
    const float* kb = g_k + (b * ND + d) * NHW;

    for (int idx = tid; idx < 4096; idx += 256) {
        const int t = idx >> 6, l = idx & 63;
        const int off = ((t >> 3) * 8 + (l >> 3)) * 64 + (t & 7) * 8 + (l & 7);
        Qs[l][t] = qb[off];
        Ks[l][t] = kb[off];
    }
    __syncthreads();

    const int ty = tid >> 4, tx = tid & 15;
    float acc[4][4];
    #pragma unroll
    for (int i = 0; i < 4; i++)
        #pragma unroll
        for (int j = 0; j < 4; j++) acc[i][j] = 0.f;

    #pragma unroll 4
    for (int l = 0; l < 64; l++) {
        float qv[4], kv[4];
        #pragma unroll
        for (int i = 0; i < 4; i++) { qv[i] = Qs[l][ty + 16 * i]; kv[i] = Ks[l][tx + 16 * i]; }
        #pragma unroll
        for (int i = 0; i < 4; i++)
            #pragma unroll
            for (int j = 0; j < 4; j++) acc[i][j] += qv[i] * kv[j];
    }

    float* part = g_ao + (b * ND + d) * NHW;
    #pragma unroll
    for (int i = 0; i < 4; i++)
        #pragma unroll
        for (int j = 0; j < 4; j++)
            part[(ty + 16 * i) * 64 + tx + 16 * j] = acc[i][j];
}

// Reduce partials over d (deterministic, no atomics). grid (16, 16), block 256.
__global__ void __launch_bounds__(256) scores_reduce_kernel()
{
    const int b  = blockIdx.y;
    const int tu = blockIdx.x * 256 + threadIdx.x;   // 0..4095
    const float* p = g_ao + b * (ND * NHW) + tu;
    float s = 0.f;
    #pragma unroll 8
    for (int d = 0; d < ND; d++) s += p[d * NHW];
    g_scores[b * 4096 + tu] = s;
}

// Softmax over the 64 key tokens. grid 16, block 64 (one thread per q-row).
__global__ void __launch_bounds__(64) softmax_kernel()
{
    const int b = blockIdx.x;
    const int t = threadIdx.x;
    const float scale = 1.0f / 128.0f;   // 1/sqrt(16384)
    const float* row = g_scores + b * 4096 + t * 64;
    float v[64];
    float m = -1e30f;
    #pragma unroll
    for (int u = 0; u < 64; u++) { v[u] = row[u] * scale; m = fmaxf(m, v[u]); }
    float s = 0.f;
    #pragma unroll
    for (int u = 0; u < 64; u++) { v[u] = __expf(v[u] - m); s += v[u]; }
    const float inv = 1.0f / s;
    float* arow = g_attn + b * 4096 + t * 64;
    #pragma unroll
    for (int u = 0; u < 64; u++) arow[u] = v[u] * inv;
}

// ---------------------------------------------------------------------------
// Kernel 3: out = attn @ V, scattered back to NCHW (overwrites g_ao).
// out[b,d,h,w] = sum_u attn[b, (h/8)*8+(w/8), u] * v[b, d, (u/8)*8 + h%8, (u%8)*8 + w%8]
// grid (64 h, 16 d-tiles, 16 b), block 256
// ---------------------------------------------------------------------------
__global__ void __launch_bounds__(256) av_kernel()
{
    const int h  = blockIdx.x;
    const int d0 = blockIdx.y * 16;
    const int b  = blockIdx.z;
    const int tid = threadIdx.x;

    __shared__ float attn_s[8][64];
    __shared__ float Vs[16][8][64];

    for (int idx = tid; idx < 512; idx += 256) {
        const int r = idx >> 6, j = idx & 63;
        attn_s[r][j] = g_attn[b * 4096 + ((h >> 3) * 8 + r) * 64 + j];
    }
    for (int idx = tid; idx < 8192; idx += 256) {
        const int dl = idx >> 9, j2 = (idx >> 6) & 7, w = idx & 63;
        Vs[dl][j2][w] = g_v[((b * ND + d0 + dl) * 64 + j2 * 8 + (h & 7)) * 64 + w];
    }
    __syncthreads();

    const int dg = (tid >> 6) * 4;
    const int w  = tid & 63;
    float acc[4] = {0.f, 0.f, 0.f, 0.f};
    #pragma unroll 8
    for (int j = 0; j < 64; j++) {
        const float a = attn_s[w >> 3][j];
        const int col = ((j & 7) << 3) | (w & 7);
        #pragma unroll
        for (int q = 0; q < 4; q++) acc[q] += a * Vs[dg + q][j >> 3][col];
    }
    #pragma unroll
    for (int q = 0; q < 4; q++)
        g_ao[((b * ND + d0 + dg + q) * 64 + h) * 64 + w] = acc[q];
}

// ---------------------------------------------------------------------------
// Kernel 4: 3x3 conv (pad 1) + bias + BN(eval) + LeakyReLU(0.2), fused.
// Block: 64 o-channels x 2 rows x 64 cols. grid (32 row-pairs, 4 o-tiles, 16 b)
// ---------------------------------------------------------------------------
__global__ void __launch_bounds__(256) conv_bn_kernel(
    const float* __restrict__ w_out, const float* __restrict__ b_out,
    const float* __restrict__ gamma, const float* __restrict__ beta,
    const float* __restrict__ bn_mean, const float* __restrict__ bn_var,
    float* __restrict__ out)
{
    const int h0 = blockIdx.x * 2;
    const int o0 = blockIdx.y * 64;
    const int b  = blockIdx.z;
    const int tid = threadIdx.x;
    const int oy = tid >> 4;    // 0..15 -> o = o0 + oy*4 + {0..3}
    const int wx = tid & 15;    // 0..15 -> w = wx*4 + {0..3}

    __shared__ float Xs[8][4][66];   // [c][row h0-1..h0+2][w (+1 pad each side)]
    __shared__ float Ws[4608];       // [o(64)][c(8)][9], flat

    float acc[4][2][4];
    #pragma unroll
    for (int oq = 0; oq < 4; oq++)
        #pragma unroll
        for (int r2 = 0; r2 < 2; r2++)
            #pragma unroll
            for (int ww = 0; ww < 4; ww++) acc[oq][r2][ww] = 0.f;

    for (int cc = 0; cc < ND; cc += 8) {
        __syncthreads();
        for (int idx = tid; idx < 2112; idx += 256) {
            const int c = idx / 264;
            const int rem = idx - c * 264;
            const int r = rem / 66;
            const int wc = rem - r * 66;
            const int row = h0 - 1 + r;
            const int ws  = wc - 1;
            float v = 0.f;
            if (row >= 0 && row < 64 && ws >= 0 && ws < 64)
                v = g_ao[((b * ND + cc + c) * 64 + row) * 64 + ws];
            Xs[c][r][wc] = v;
        }
        for (int idx = tid; idx < 4608; idx += 256) {
            const int o = idx / 72;
            const int rem = idx - o * 72;       // c*9 + k
            Ws[idx] = w_out[((o0 + o) * ND + cc + rem / 9) * 9 + rem % 9];
        }
        __syncthreads();

        #pragma unroll
        for (int c = 0; c < 8; c++) {
            #pragma unroll
            for (int kh = 0; kh < 3; kh++) {
                float xv[2][6];
                #pragma unroll
                for (int r2 = 0; r2 < 2; r2++)
                    #pragma unroll
                    for (int ii = 0; ii < 6; ii++)
                        xv[r2][ii] = Xs[c][kh + r2][wx * 4 + ii];
                float wv[3][4];
                #pragma unroll
                for (int kw = 0; kw < 3; kw++)
                    #pragma unroll
                    for (int oq = 0; oq < 4; oq++)
                        wv[kw][oq] = Ws[(oy * 4 + oq) * 72 + c * 9 + kh * 3 + kw];
                #pragma unroll
                for (int oq = 0; oq < 4; oq++)
                    #pragma unroll
                    for (int r2 = 0; r2 < 2; r2++)
                        #pragma unroll
                        for (int ww = 0; ww < 4; ww++)
                            #pragma unroll
                            for (int kw = 0; kw < 3; kw++)
                                acc[oq][r2][ww] += wv[kw][oq] * xv[r2][ww + kw];
            }
        }
    }

    #pragma unroll
    for (int oq = 0; oq < 4; oq++) {
        const int o = o0 + oy * 4 + oq;
        const float sc  = gamma[o] * rsqrtf(bn_var[o] + 1e-5f);
        const float add = (b_out[o] - bn_mean[o]) * sc + beta[o];
        #pragma unroll
        for (int r2 = 0; r2 < 2; r2++) {
            float4 r;
            float t0 = acc[oq][r2][0] * sc + add;
            float t1 = acc[oq][r2][1] * sc + add;
            float t2 = acc[oq][r2][2] * sc + add;
            float t3 = acc[oq][r2][3] * sc + add;
            r.x = (t0 >= 0.f) ? t0 : 0.2f * t0;
            r.y = (t1 >= 0.f) ? t1 : 0.2f * t1;
            r.z = (t2 >= 0.f) ? t2 : 0.2f * t2;
            r.w = (t3 >= 0.f) ? t3 : 0.2f * t3;
            *(float4*)(out + ((b * ND + o) * 64 + h0 + r2) * 64 + wx * 4) = r;
        }
    }
}

// ---------------------------------------------------------------------------
extern "C" void kernel_launch(void* const* d_in, const int* in_sizes, int n_in,
                              void* d_out, int out_size)
{
    const float* x       = (const float*)d_in[0];
    const float* wq      = (const float*)d_in[1];
    const float* bq      = (const float*)d_in[2];
    const float* wk      = (const float*)d_in[3];
    const float* bk      = (const float*)d_in[4];
    const float* wv      = (const float*)d_in[5];
    const float* bv      = (const float*)d_in[6];
    const float* w_out   = (const float*)d_in[7];
    const float* b_out   = (const float*)d_in[8];
    const float* gamma   = (const float*)d_in[9];
    const float* beta    = (const float*)d_in[10];
    const float* bn_mean = (const float*)d_in[11];
    const float* bn_var  = (const float*)d_in[12];
    float* out = (float*)d_out;

    qkv_kernel<<<dim3(32, 2, 48), 256>>>(x, wq, bq, wk, bk, wv, bv);
    scores_partial_kernel<<<dim3(256, 16), 256>>>();
    scores_reduce_kernel<<<dim3(16, 16), 256>>>();
    softmax_kernel<<<16, 64>>>();
    av_kernel<<<dim3(64, 16, 16), 256>>>();
    conv_bn_kernel<<<dim3(32, 4, 16), 256>>>(w_out, b_out, gamma, beta, bn_mean, bn_var, out);
}

// round 3
// speedup vs baseline: 2.2880x; 2.2880x over previous
#include <cuda_runtime.h>
#include <cuda_bf16.h>
#include <cstdint>
#include <math.h>

#define NB 16
#define ND 256
#define NPIX 4096

// ---------------- global scratch (allocation-free) ----------------
__device__ float g_q [NB*ND*NPIX];
__device__ float g_k [NB*ND*NPIX];
__device__ float g_v [NB*ND*NPIX];
__device__ float g_ao[NB*ND*NPIX];
__device__ float g_scores[NB*64*64];
__device__ float g_attn  [NB*64*64];

__device__ __align__(16) __nv_bfloat16 g_xt_hi [NB*NPIX*ND];
__device__ __align__(16) __nv_bfloat16 g_xt_lo [NB*NPIX*ND];
__device__ __align__(16) __nv_bfloat16 g_aot_hi[NB*NPIX*ND];
__device__ __align__(16) __nv_bfloat16 g_aot_lo[NB*NPIX*ND];
__device__ __align__(16) __nv_bfloat16 g_wp_hi[3*ND*ND];
__device__ __align__(16) __nv_bfloat16 g_wp_lo[3*ND*ND];
__device__ __align__(16) __nv_bfloat16 g_wc_hi[9*ND*ND];
__device__ __align__(16) __nv_bfloat16 g_wc_lo[9*ND*ND];

// ---------------- helpers ----------------
__device__ __forceinline__ uint32_t smem_u32(const void* p){
    uint32_t a;
    asm("{ .reg .u64 t; cvta.to.shared.u64 t, %1; cvt.u32.u64 %0, t; }" : "=r"(a) : "l"(p));
    return a;
}
__device__ __forceinline__ int fsw(int m){ return (m & 3) ^ ((m >> 2) & 1); }

__device__ __forceinline__ void cp16(uint32_t saddr, const void* gaddr, bool v){
    asm volatile("cp.async.ca.shared.global [%0], [%1], 16, %2;"
        :: "r"(saddr), "l"(gaddr), "r"(v ? 16 : 0));
}
#define CP_COMMIT() asm volatile("cp.async.commit_group;" ::: "memory")
#define CP_WAIT1()  asm volatile("cp.async.wait_group 1;" ::: "memory")
#define CP_WAIT0()  asm volatile("cp.async.wait_group 0;" ::: "memory")

__device__ __forceinline__ void ldmat4(uint32_t* r, uint32_t addr){
    asm volatile("ldmatrix.sync.aligned.m8n8.x4.shared.b16 {%0,%1,%2,%3}, [%4];"
        : "=r"(r[0]), "=r"(r[1]), "=r"(r[2]), "=r"(r[3]) : "r"(addr));
}
__device__ __forceinline__ void mma16816(float* d, const uint32_t* a, const uint32_t* b){
    asm volatile("mma.sync.aligned.m16n8k16.row.col.f32.bf16.bf16.f32 "
        "{%0,%1,%2,%3}, {%4,%5,%6,%7}, {%8,%9}, {%0,%1,%2,%3};"
        : "+f"(d[0]), "+f"(d[1]), "+f"(d[2]), "+f"(d[3])
        : "r"(a[0]), "r"(a[1]), "r"(a[2]), "r"(a[3]), "r"(b[0]), "r"(b[1]));
}

#define SMEM_BYTES (3*32768)

// ---------------- split / transpose kernels ----------------
template<int SRC>
__global__ void __launch_bounds__(256) split_transpose_kernel(const float* __restrict__ xsrc)
{
    const float* src = (SRC == 0) ? xsrc : g_ao;
    __nv_bfloat16* dh = (SRC == 0) ? g_xt_hi : g_aot_hi;
    __nv_bfloat16* dl = (SRC == 0) ? g_xt_lo : g_aot_lo;
    const int b = blockIdx.z, c0 = blockIdx.y * 32, p0 = blockIdx.x * 32;
    __shared__ float tile[32][33];
    const int tx = threadIdx.x & 31, ty = threadIdx.x >> 5;
    const float* s = src + ((size_t)b * ND + c0) * NPIX + p0;
    #pragma unroll
    for (int i = 0; i < 32; i += 8)
        tile[ty + i][tx] = s[(size_t)(ty + i) * NPIX + tx];
    __syncthreads();
    #pragma unroll
    for (int i = 0; i < 32; i += 8) {
        float v = tile[tx][ty + i];
        __nv_bfloat16 h = __float2bfloat16(v);
        __nv_bfloat16 l = __float2bfloat16(v - __bfloat162float(h));
        size_t di = ((size_t)b * NPIX + p0 + ty + i) * ND + c0 + tx;
        dh[di] = h; dl[di] = l;
    }
}

__global__ void __launch_bounds__(256) split_wqkv_kernel(
    const float* __restrict__ wq, const float* __restrict__ wk, const float* __restrict__ wv)
{
    int i = blockIdx.x * 256 + threadIdx.x;           // 196608 total
    const float* w = (i < 65536) ? wq : (i < 131072) ? wk : wv;
    float v = w[i & 65535];
    __nv_bfloat16 h = __float2bfloat16(v);
    g_wp_hi[i] = h;
    g_wp_lo[i] = __float2bfloat16(v - __bfloat162float(h));
}

__global__ void __launch_bounds__(256) split_wconv_kernel(const float* __restrict__ w_out)
{
    int i = blockIdx.x * 256 + threadIdx.x;           // 589824 total
    float v = w_out[i];
    int o = i / 2304; int rem = i - o * 2304; int c = rem / 9; int khw = rem - c * 9;
    size_t di = (size_t)khw * 65536 + (size_t)o * 256 + c;
    __nv_bfloat16 h = __float2bfloat16(v);
    g_wc_hi[di] = h;
    g_wc_lo[di] = __float2bfloat16(v - __bfloat162float(h));
}

// ---------------- QKV mma.sync GEMM ----------------
// C[o, pix] = W[o, c] * Xt[pix, c]; block tile 128x128, K=256 in 8 k32 stages.
__global__ void __launch_bounds__(256) qkv_mma_kernel(
    const float* __restrict__ bq, const float* __restrict__ bk, const float* __restrict__ bv)
{
    extern __shared__ char smem[];
    const uint32_t sbase = smem_u32(smem);
    const int tid = threadIdx.x;
    const int lane = tid & 31, wid = tid >> 5;
    const int wm = wid >> 2, wn = wid & 3;
    const int n0 = blockIdx.x * 128, o0 = blockIdx.y * 128;
    const int proj = blockIdx.z % 3, b = blockIdx.z / 3;

    const __nv_bfloat16* Ahi = g_wp_hi + (size_t)proj * 65536;
    const __nv_bfloat16* Alo = g_wp_lo + (size_t)proj * 65536;
    const __nv_bfloat16* Bhi = g_xt_hi + (size_t)b * NPIX * ND;
    const __nv_bfloat16* Blo = g_xt_lo + (size_t)b * NPIX * ND;

    float acc[4][4][4];
    #pragma unroll
    for (int i = 0; i < 4; i++)
        #pragma unroll
        for (int j = 0; j < 4; j++)
            #pragma unroll
            for (int q = 0; q < 4; q++) acc[i][j][q] = 0.f;

    auto load_stage = [&](int s, int buf) {
        const uint32_t stb = sbase + buf * 32768;
        const int k0 = s * 32;
        #pragma unroll
        for (int q = 0; q < 2; q++) {
            const int g = tid + q * 256;
            const int m = g >> 2, c = g & 3;
            const uint32_t so = (uint32_t)(m * 64 + ((c ^ fsw(m)) << 4));
            const size_t aoff = (size_t)(o0 + m) * 256 + k0 + c * 8;
            const size_t boff = (size_t)(n0 + m) * 256 + k0 + c * 8;
            cp16(stb + so,          Ahi + aoff, true);
            cp16(stb + 8192 + so,   Alo + aoff, true);
            cp16(stb + 16384 + so,  Bhi + boff, true);
            cp16(stb + 24576 + so,  Blo + boff, true);
        }
        CP_COMMIT();
    };

    auto compute_stage = [&](int buf) {
        const uint32_t stb = sbase + buf * 32768;
        #pragma unroll
        for (int kh = 0; kh < 2; kh++) {
            uint32_t ah[4][4], al[4][4], bhf[4][2], blf[4][2];
            #pragma unroll
            for (int i = 0; i < 4; i++) {
                const int row = wm * 64 + i * 16 + (lane & 15);
                const int ch = (2 * kh + (lane >> 4)) ^ fsw(row);
                const uint32_t ad = stb + row * 64 + ch * 16;
                ldmat4(ah[i], ad);
                ldmat4(al[i], ad + 8192);
            }
            #pragma unroll
            for (int jj = 0; jj < 2; jj++) {
                const int row = wn * 32 + jj * 16 + (lane & 7) + ((lane >> 4) << 3);
                const int ch = (2 * kh + ((lane >> 3) & 1)) ^ fsw(row);
                const uint32_t ad = stb + 16384 + row * 64 + ch * 16;
                uint32_t r4[4];
                ldmat4(r4, ad);
                bhf[2*jj][0] = r4[0]; bhf[2*jj][1] = r4[1];
                bhf[2*jj+1][0] = r4[2]; bhf[2*jj+1][1] = r4[3];
                ldmat4(r4, ad + 8192);
                blf[2*jj][0] = r4[0]; blf[2*jj][1] = r4[1];
                blf[2*jj+1][0] = r4[2]; blf[2*jj+1][1] = r4[3];
            }
            #pragma unroll
            for (int i = 0; i < 4; i++)
                #pragma unroll
                for (int j = 0; j < 4; j++) {
                    mma16816(acc[i][j], ah[i], bhf[j]);
                    mma16816(acc[i][j], ah[i], blf[j]);
                    mma16816(acc[i][j], al[i], bhf[j]);
                }
        }
    };

    load_stage(0, 0);
    load_stage(1, 1);
    #pragma unroll 1
    for (int s = 0; s < 8; s++) {
        if (s + 1 < 8) { CP_WAIT1(); } else { CP_WAIT0(); }
        __syncthreads();
        if (s + 2 < 8) load_stage(s + 2, (s + 2) % 3);
        compute_stage(s % 3);
    }

    const float* bias = (proj == 0) ? bq : (proj == 1) ? bk : bv;
    float* dst = ((proj == 0) ? g_q : (proj == 1) ? g_k : g_v) + (size_t)b * ND * NPIX;
    #pragma unroll
    for (int i = 0; i < 4; i++) {
        const int r0 = o0 + wm * 64 + i * 16 + (lane >> 2);
        const float bb0 = bias[r0], bb1 = bias[r0 + 8];
        #pragma unroll
        for (int j = 0; j < 4; j++) {
            const int cb = n0 + wn * 32 + j * 8 + 2 * (lane & 3);
            float2 v0 = make_float2(acc[i][j][0] + bb0, acc[i][j][1] + bb0);
            float2 v1 = make_float2(acc[i][j][2] + bb1, acc[i][j][3] + bb1);
            *(float2*)(dst + (size_t)r0 * NPIX + cb) = v0;
            *(float2*)(dst + (size_t)(r0 + 8) * NPIX + cb) = v1;
        }
    }
}

// ---------------- conv 3x3 implicit GEMM + BN + LeakyReLU ----------------
__global__ void __launch_bounds__(256) conv_mma_kernel(
    const float* __restrict__ b_out, const float* __restrict__ gamma,
    const float* __restrict__ beta,  const float* __restrict__ bn_mean,
    const float* __restrict__ bn_var, float* __restrict__ out)
{
    extern __shared__ char smem[];
    const uint32_t sbase = smem_u32(smem);
    const int tid = threadIdx.x;
    const int lane = tid & 31, wid = tid >> 5;
    const int wm = wid >> 2, wn = wid & 3;
    const int n0 = blockIdx.x * 128, o0 = blockIdx.y * 128;
    const int b = blockIdx.z;

    const __nv_bfloat16* Bhi = g_aot_hi + (size_t)b * NPIX * ND;
    const __nv_bfloat16* Blo = g_aot_lo + (size_t)b * NPIX * ND;

    float acc[4][4][4];
    #pragma unroll
    for (int i = 0; i < 4; i++)
        #pragma unroll
        for (int j = 0; j < 4; j++)
            #pragma unroll
            for (int q = 0; q < 4; q++) acc[i][j][q] = 0.f;

    auto load_stage = [&](int s, int buf) {
        const uint32_t stb = sbase + buf * 32768;
        const int khw = s >> 3, kc = s & 7;
        const int dh = khw / 3 - 1, dw = khw % 3 - 1;
        const int k0 = kc * 32;
        #pragma unroll
        for (int q = 0; q < 2; q++) {
            const int g = tid + q * 256;
            const int m = g >> 2, c = g & 3;
            const uint32_t so = (uint32_t)(m * 64 + ((c ^ fsw(m)) << 4));
            const size_t aoff = (size_t)khw * 65536 + (size_t)(o0 + m) * 256 + k0 + c * 8;
            cp16(stb + so,        g_wc_hi + aoff, true);
            cp16(stb + 8192 + so, g_wc_lo + aoff, true);
            const int p = n0 + m;
            const int h2 = (p >> 6) + dh, w2 = (p & 63) + dw;
            const bool v = ((unsigned)h2 < 64u) && ((unsigned)w2 < 64u);
            const size_t boff = (size_t)(v ? (h2 * 64 + w2) : 0) * 256 + k0 + c * 8;
            cp16(stb + 16384 + so, Bhi + boff, v);
            cp16(stb + 24576 + so, Blo + boff, v);
        }
        CP_COMMIT();
    };

    auto compute_stage = [&](int buf) {
        const uint32_t stb = sbase + buf * 32768;
        #pragma unroll
        for (int kh = 0; kh < 2; kh++) {
            uint32_t ah[4][4], al[4][4], bhf[4][2], blf[4][2];
            #pragma unroll
            for (int i = 0; i < 4; i++) {
                const int row = wm * 64 + i * 16 + (lane & 15);
                const int ch = (2 * kh + (lane >> 4)) ^ fsw(row);
                const uint32_t ad = stb + row * 64 + ch * 16;
                ldmat4(ah[i], ad);
                ldmat4(al[i], ad + 8192);
            }
            #pragma unroll
            for (int jj = 0; jj < 2; jj++) {
                const int row = wn * 32 + jj * 16 + (lane & 7) + ((lane >> 4) << 3);
                const int ch = (2 * kh + ((lane >> 3) & 1)) ^ fsw(row);
                const uint32_t ad = stb + 16384 + row * 64 + ch * 16;
                uint32_t r4[4];
                ldmat4(r4, ad);
                bhf[2*jj][0] = r4[0]; bhf[2*jj][1] = r4[1];
                bhf[2*jj+1][0] = r4[2]; bhf[2*jj+1][1] = r4[3];
                ldmat4(r4, ad + 8192);
                blf[2*jj][0] = r4[0]; blf[2*jj][1] = r4[1];
                blf[2*jj+1][0] = r4[2]; blf[2*jj+1][1] = r4[3];
            }
            #pragma unroll
            for (int i = 0; i < 4; i++)
                #pragma unroll
                for (int j = 0; j < 4; j++) {
                    mma16816(acc[i][j], ah[i], bhf[j]);
                    mma16816(acc[i][j], ah[i], blf[j]);
                    mma16816(acc[i][j], al[i], bhf[j]);
                }
        }
    };

    load_stage(0, 0);
    load_stage(1, 1);
    #pragma unroll 1
    for (int s = 0; s < 72; s++) {
        if (s + 1 < 72) { CP_WAIT1(); } else { CP_WAIT0(); }
        __syncthreads();
        if (s + 2 < 72) load_stage(s + 2, (s + 2) % 3);
        compute_stage(s % 3);
    }

    float* dst = out + (size_t)b * ND * NPIX;
    #pragma unroll
    for (int i = 0; i < 4; i++) {
        const int r0 = o0 + wm * 64 + i * 16 + (lane >> 2);
        const float sc0 = gamma[r0]     * rsqrtf(bn_var[r0]     + 1e-5f);
        const float sc1 = gamma[r0 + 8] * rsqrtf(bn_var[r0 + 8] + 1e-5f);
        const float ad0 = (b_out[r0]     - bn_mean[r0])     * sc0 + beta[r0];
        const float ad1 = (b_out[r0 + 8] - bn_mean[r0 + 8]) * sc1 + beta[r0 + 8];
        #pragma unroll
        for (int j = 0; j < 4; j++) {
            const int cb = n0 + wn * 32 + j * 8 + 2 * (lane & 3);
            float t0 = acc[i][j][0] * sc0 + ad0;
            float t1 = acc[i][j][1] * sc0 + ad0;
            float t2 = acc[i][j][2] * sc1 + ad1;
            float t3 = acc[i][j][3] * sc1 + ad1;
            float2 v0 = make_float2((t0 >= 0.f) ? t0 : 0.2f * t0,
                                    (t1 >= 0.f) ? t1 : 0.2f * t1);
            float2 v1 = make_float2((t2 >= 0.f) ? t2 : 0.2f * t2,
                                    (t3 >= 0.f) ? t3 : 0.2f * t3);
            *(float2*)(dst + (size_t)r0 * NPIX + cb) = v0;
            *(float2*)(dst + (size_t)(r0 + 8) * NPIX + cb) = v1;
        }
    }
}

// ---------------- attention middle (SIMT) ----------------
__global__ void __launch_bounds__(256) scores_partial_kernel()
{
    const int d = blockIdx.x;
    const int b = blockIdx.y;
    const int tid = threadIdx.x;
    __shared__ float Qs[64][65];
    __shared__ float Ks[64][65];
    const float* qb = g_q + ((size_t)b * ND + d) * NPIX;
    const float* kb = g_k + ((size_t)b * ND + d) * NPIX;

    for (int idx = tid; idx < 4096; idx += 256) {
        const int t = idx >> 6, l = idx & 63;
        const int off = ((t >> 3) * 8 + (l >> 3)) * 64 + (t & 7) * 8 + (l & 7);
        Qs[l][t] = qb[off];
        Ks[l][t] = kb[off];
    }
    __syncthreads();

    const int ty = tid >> 4, tx = tid & 15;
    float acc[4][4];
    #pragma unroll
    for (int i = 0; i < 4; i++)
        #pragma unroll
        for (int j = 0; j < 4; j++) acc[i][j] = 0.f;

    #pragma unroll 4
    for (int l = 0; l < 64; l++) {
        float qv[4], kv[4];
        #pragma unroll
        for (int i = 0; i < 4; i++) { qv[i] = Qs[l][ty + 16*i]; kv[i] = Ks[l][tx + 16*i]; }
        #pragma unroll
        for (int i = 0; i < 4; i++)
            #pragma unroll
            for (int j = 0; j < 4; j++) acc[i][j] += qv[i] * kv[j];
    }

    float* part = g_ao + ((size_t)b * ND + d) * NPIX;
    #pragma unroll
    for (int i = 0; i < 4; i++)
        #pragma unroll
        for (int j = 0; j < 4; j++)
            part[(ty + 16*i) * 64 + tx + 16*j] = acc[i][j];
}

__global__ void __launch_bounds__(256) scores_reduce_kernel()
{
    const int b  = blockIdx.y;
    const int tu = blockIdx.x * 256 + threadIdx.x;
    const float* pp = g_ao + (size_t)b * ND * NPIX + tu;
    float s = 0.f;
    #pragma unroll 8
    for (int d = 0; d < ND; d++) s += pp[(size_t)d * NPIX];
    g_scores[b * 4096 + tu] = s;
}

__global__ void __launch_bounds__(64) softmax_kernel()
{
    const int b = blockIdx.x;
    const int t = threadIdx.x;
    const float scale = 1.0f / 128.0f;
    const float* row = g_scores + b * 4096 + t * 64;
    float v[64];
    float m = -1e30f;
    #pragma unroll
    for (int u = 0; u < 64; u++) { v[u] = row[u] * scale; m = fmaxf(m, v[u]); }
    float s = 0.f;
    #pragma unroll
    for (int u = 0; u < 64; u++) { v[u] = __expf(v[u] - m); s += v[u]; }
    const float inv = 1.0f / s;
    float* arow = g_attn + b * 4096 + t * 64;
    #pragma unroll
    for (int u = 0; u < 64; u++) arow[u] = v[u] * inv;
}

__global__ void __launch_bounds__(256) av_kernel()
{
    const int h  = blockIdx.x;
    const int d0 = blockIdx.y * 16;
    const int b  = blockIdx.z;
    const int tid = threadIdx.x;

    __shared__ float attn_s[8][64];
    __shared__ float Vs[16][8][64];

    for (int idx = tid; idx < 512; idx += 256) {
        const int r = idx >> 6, j = idx & 63;
        attn_s[r][j] = g_attn[b * 4096 + ((h >> 3) * 8 + r) * 64 + j];
    }
    for (int idx = tid; idx < 8192; idx += 256) {
        const int dl = idx >> 9, j2 = (idx >> 6) & 7, w = idx & 63;
        Vs[dl][j2][w] = g_v[(((size_t)b * ND + d0 + dl) * 64 + j2 * 8 + (h & 7)) * 64 + w];
    }
    __syncthreads();

    const int dg = (tid >> 6) * 4;
    const int w  = tid & 63;
    float acc[4] = {0.f, 0.f, 0.f, 0.f};
    #pragma unroll 8
    for (int j = 0; j < 64; j++) {
        const float a = attn_s[w >> 3][j];
        const int col = ((j & 7) << 3) | (w & 7);
        #pragma unroll
        for (int q = 0; q < 4; q++) acc[q] += a * Vs[dg + q][j >> 3][col];
    }
    #pragma unroll
    for (int q = 0; q < 4; q++)
        g_ao[(((size_t)b * ND + d0 + dg + q) * 64 + h) * 64 + w] = acc[q];
}

// ---------------- host ----------------
extern "C" void kernel_launch(void* const* d_in, const int* in_sizes, int n_in,
                              void* d_out, int out_size)
{
    const float* x       = (const float*)d_in[0];
    const float* wq      = (const float*)d_in[1];
    const float* bq      = (const float*)d_in[2];
    const float* wk      = (const float*)d_in[3];
    const float* bk      = (const float*)d_in[4];
    const float* wv      = (const float*)d_in[5];
    const float* bv      = (const float*)d_in[6];
    const float* w_out   = (const float*)d_in[7];
    const float* b_out   = (const float*)d_in[8];
    const float* gamma   = (const float*)d_in[9];
    const float* beta    = (const float*)d_in[10];
    const float* bn_mean = (const float*)d_in[11];
    const float* bn_var  = (const float*)d_in[12];
    float* out = (float*)d_out;

    cudaFuncSetAttribute(qkv_mma_kernel,  cudaFuncAttributeMaxDynamicSharedMemorySize, SMEM_BYTES);
    cudaFuncSetAttribute(conv_mma_kernel, cudaFuncAttributeMaxDynamicSharedMemorySize, SMEM_BYTES);

    split_wqkv_kernel <<<768,  256>>>(wq, wk, wv);
    split_wconv_kernel<<<2304, 256>>>(w_out);
    split_transpose_kernel<0><<<dim3(128, 8, 16), 256>>>(x);

    qkv_mma_kernel<<<dim3(32, 2, 48), 256, SMEM_BYTES>>>(bq, bk, bv);

    scores_partial_kernel<<<dim3(256, 16), 256>>>();
    scores_reduce_kernel <<<dim3(16, 16), 256>>>();
    softmax_kernel<<<16, 64>>>();
    av_kernel<<<dim3(64, 16, 16), 256>>>();

    split_transpose_kernel<1><<<dim3(128, 8, 16), 256>>>(nullptr);
    conv_mma_kernel<<<dim3(32, 2, 16), 256, SMEM_BYTES>>>(b_out, gamma, beta, bn_mean, bn_var, out);
}

// round 4
// speedup vs baseline: 4.0553x; 1.7724x over previous
#include <cuda_runtime.h>
#include <cuda_fp16.h>
#include <cstdint>
#include <math.h>

#define NB 16
#define ND 256
#define NPIX 4096

// ---------------- global scratch (allocation-free) ----------------
__device__ float g_q [NB*ND*NPIX];
__device__ float g_k [NB*ND*NPIX];
__device__ float g_v [NB*ND*NPIX];
__device__ float g_ao[NB*ND*NPIX];
__device__ float g_scores[NB*64*64];
__device__ float g_attn  [NB*64*64];

__device__ __align__(16) __half g_xt [NB*NPIX*ND];   // x transposed [b][pix][c], fp16
__device__ __align__(16) __half g_aot[NB*NPIX*ND];   // attn out transposed, fp16
__device__ __align__(16) __half g_wp [3*ND*ND];      // qkv weights [proj][o][c]
__device__ __align__(16) __half g_wc [9*ND*ND];      // conv weights [khw][o][c]

// ---------------- helpers ----------------
__device__ __forceinline__ uint32_t smem_u32(const void* p){
    uint32_t a;
    asm("{ .reg .u64 t; cvta.to.shared.u64 t, %1; cvt.u32.u64 %0, t; }" : "=r"(a) : "l"(p));
    return a;
}
__device__ __forceinline__ void cp16(uint32_t saddr, const void* gaddr, bool v){
    asm volatile("cp.async.ca.shared.global [%0], [%1], 16, %2;"
        :: "r"(saddr), "l"(gaddr), "r"(v ? 16 : 0));
}
#define CP_COMMIT() asm volatile("cp.async.commit_group;" ::: "memory")
#define CP_WAIT1()  asm volatile("cp.async.wait_group 1;" ::: "memory")
#define CP_WAIT0()  asm volatile("cp.async.wait_group 0;" ::: "memory")

__device__ __forceinline__ void ldmat4(uint32_t* r, uint32_t addr){
    asm volatile("ldmatrix.sync.aligned.m8n8.x4.shared.b16 {%0,%1,%2,%3}, [%4];"
        : "=r"(r[0]), "=r"(r[1]), "=r"(r[2]), "=r"(r[3]) : "r"(addr));
}
__device__ __forceinline__ void mma16816(float* d, const uint32_t* a, const uint32_t* b){
    asm volatile("mma.sync.aligned.m16n8k16.row.col.f32.f16.f16.f32 "
        "{%0,%1,%2,%3}, {%4,%5,%6,%7}, {%8,%9}, {%0,%1,%2,%3};"
        : "+f"(d[0]), "+f"(d[1]), "+f"(d[2]), "+f"(d[3])
        : "r"(a[0]), "r"(a[1]), "r"(a[2]), "r"(a[3]), "r"(b[0]), "r"(b[1]));
}

// stage: A[128 rows][64 k] fp16 (16KB, 128B rows) + B same -> 32KB; 3 stages = 96KB
#define STAGE_BYTES 32768
#define SMEM_BYTES  (3*STAGE_BYTES)

// ---------------- convert / transpose kernels ----------------
template<int SRC>
__global__ void __launch_bounds__(256) convert_transpose_kernel(const float* __restrict__ xsrc)
{
    const float* src = (SRC == 0) ? xsrc : g_ao;
    __half* dh = (SRC == 0) ? g_xt : g_aot;
    const int b = blockIdx.z, c0 = blockIdx.y * 32, p0 = blockIdx.x * 32;
    __shared__ float tile[32][33];
    const int tx = threadIdx.x & 31, ty = threadIdx.x >> 5;
    const float* s = src + ((size_t)b * ND + c0) * NPIX + p0;
    #pragma unroll
    for (int i = 0; i < 32; i += 8)
        tile[ty + i][tx] = s[(size_t)(ty + i) * NPIX + tx];
    __syncthreads();
    #pragma unroll
    for (int i = 0; i < 32; i += 8) {
        size_t di = ((size_t)b * NPIX + p0 + ty + i) * ND + c0 + tx;
        dh[di] = __float2half_rn(tile[tx][ty + i]);
    }
}

__global__ void __launch_bounds__(256) convert_wqkv_kernel(
    const float* __restrict__ wq, const float* __restrict__ wk, const float* __restrict__ wv)
{
    int i = blockIdx.x * 256 + threadIdx.x;           // 196608 total
    const float* w = (i < 65536) ? wq : (i < 131072) ? wk : wv;
    g_wp[i] = __float2half_rn(w[i & 65535]);
}

__global__ void __launch_bounds__(256) convert_wconv_kernel(const float* __restrict__ w_out)
{
    int i = blockIdx.x * 256 + threadIdx.x;           // 589824 total
    float v = w_out[i];
    int o = i / 2304; int rem = i - o * 2304; int c = rem / 9; int khw = rem - c * 9;
    g_wc[(size_t)khw * 65536 + (size_t)o * 256 + c] = __float2half_rn(v);
}

// ---------------- QKV mma.sync GEMM (fp16, single term) ----------------
// C[o, pix] = W[o, c] * Xt[pix, c]; block tile 128x128, K=256 in 4 k64 stages.
__global__ void __launch_bounds__(256, 2) qkv_mma_kernel(
    const float* __restrict__ bq, const float* __restrict__ bk, const float* __restrict__ bv)
{
    extern __shared__ char smem[];
    const uint32_t sbase = smem_u32(smem);
    const int tid = threadIdx.x;
    const int lane = tid & 31, wid = tid >> 5;
    const int wm = wid >> 2, wn = wid & 3;
    const int n0 = blockIdx.x * 128, o0 = blockIdx.y * 128;
    const int proj = blockIdx.z % 3, b = blockIdx.z / 3;

    const __half* A = g_wp + (size_t)proj * 65536;
    const __half* B = g_xt + (size_t)b * NPIX * ND;

    float acc[4][4][4];
    #pragma unroll
    for (int i = 0; i < 4; i++)
        #pragma unroll
        for (int j = 0; j < 4; j++)
            #pragma unroll
            for (int q = 0; q < 4; q++) acc[i][j][q] = 0.f;

    auto load_stage = [&](int s, int buf) {
        const uint32_t stb = sbase + buf * STAGE_BYTES;
        const int k0 = s * 64;
        #pragma unroll
        for (int q = 0; q < 8; q++) {
            const int g = tid + q * 256;          // 0..2047
            const int arr = g >> 10;              // 0 = A, 1 = B
            const int idx = g & 1023;
            const int m = idx >> 3, c = idx & 7;
            const uint32_t so = (uint32_t)(arr * 16384 + m * 128 + ((c ^ (m & 7)) << 4));
            const size_t off = (size_t)((arr ? n0 : o0) + m) * 256 + k0 + c * 8;
            cp16(stb + so, (arr ? B : A) + off, true);
        }
        CP_COMMIT();
    };

    auto compute_stage = [&](int buf) {
        const uint32_t stb = sbase + buf * STAGE_BYTES;
        #pragma unroll
        for (int kh = 0; kh < 4; kh++) {
            uint32_t ah[4][4], bf[4][2];
            #pragma unroll
            for (int i = 0; i < 4; i++) {
                const int row = wm * 64 + i * 16 + (lane & 15);
                const int ch = (2 * kh + (lane >> 4)) ^ (row & 7);
                ldmat4(ah[i], stb + row * 128 + ch * 16);
            }
            #pragma unroll
            for (int jj = 0; jj < 2; jj++) {
                const int row = wn * 32 + jj * 16 + (lane & 7) + ((lane >> 4) << 3);
                const int ch = (2 * kh + ((lane >> 3) & 1)) ^ (row & 7);
                uint32_t r4[4];
                ldmat4(r4, stb + 16384 + row * 128 + ch * 16);
                bf[2*jj][0] = r4[0]; bf[2*jj][1] = r4[1];
                bf[2*jj+1][0] = r4[2]; bf[2*jj+1][1] = r4[3];
            }
            #pragma unroll
            for (int i = 0; i < 4; i++)
                #pragma unroll
                for (int j = 0; j < 4; j++)
                    mma16816(acc[i][j], ah[i], bf[j]);
        }
    };

    load_stage(0, 0);
    load_stage(1, 1);
    #pragma unroll 1
    for (int s = 0; s < 4; s++) {
        if (s + 1 < 4) { CP_WAIT1(); } else { CP_WAIT0(); }
        __syncthreads();
        if (s + 2 < 4) load_stage(s + 2, (s + 2) % 3);
        compute_stage(s % 3);
    }

    const float* bias = (proj == 0) ? bq : (proj == 1) ? bk : bv;
    float* dst = ((proj == 0) ? g_q : (proj == 1) ? g_k : g_v) + (size_t)b * ND * NPIX;
    #pragma unroll
    for (int i = 0; i < 4; i++) {
        const int r0 = o0 + wm * 64 + i * 16 + (lane >> 2);
        const float bb0 = bias[r0], bb1 = bias[r0 + 8];
        #pragma unroll
        for (int j = 0; j < 4; j++) {
            const int cb = n0 + wn * 32 + j * 8 + 2 * (lane & 3);
            float2 v0 = make_float2(acc[i][j][0] + bb0, acc[i][j][1] + bb0);
            float2 v1 = make_float2(acc[i][j][2] + bb1, acc[i][j][3] + bb1);
            *(float2*)(dst + (size_t)r0 * NPIX + cb) = v0;
            *(float2*)(dst + (size_t)(r0 + 8) * NPIX + cb) = v1;
        }
    }
}

// ---------------- conv 3x3 implicit GEMM + BN + LeakyReLU (fp16) ----------------
__global__ void __launch_bounds__(256, 2) conv_mma_kernel(
    const float* __restrict__ b_out, const float* __restrict__ gamma,
    const float* __restrict__ beta,  const float* __restrict__ bn_mean,
    const float* __restrict__ bn_var, float* __restrict__ out)
{
    extern __shared__ char smem[];
    const uint32_t sbase = smem_u32(smem);
    const int tid = threadIdx.x;
    const int lane = tid & 31, wid = tid >> 5;
    const int wm = wid >> 2, wn = wid & 3;
    const int n0 = blockIdx.x * 128, o0 = blockIdx.y * 128;
    const int b = blockIdx.z;

    const __half* B = g_aot + (size_t)b * NPIX * ND;

    float acc[4][4][4];
    #pragma unroll
    for (int i = 0; i < 4; i++)
        #pragma unroll
        for (int j = 0; j < 4; j++)
            #pragma unroll
            for (int q = 0; q < 4; q++) acc[i][j][q] = 0.f;

    auto load_stage = [&](int s, int buf) {
        const uint32_t stb = sbase + buf * STAGE_BYTES;
        const int khw = s >> 2, kc = s & 3;
        const int dh = khw / 3 - 1, dw = khw % 3 - 1;
        const int k0 = kc * 64;
        #pragma unroll
        for (int q = 0; q < 8; q++) {
            const int g = tid + q * 256;
            const int arr = g >> 10;
            const int idx = g & 1023;
            const int m = idx >> 3, c = idx & 7;
            const uint32_t so = (uint32_t)(arr * 16384 + m * 128 + ((c ^ (m & 7)) << 4));
            if (arr == 0) {
                const size_t aoff = (size_t)khw * 65536 + (size_t)(o0 + m) * 256 + k0 + c * 8;
                cp16(stb + so, g_wc + aoff, true);
            } else {
                const int p = n0 + m;
                const int h2 = (p >> 6) + dh, w2 = (p & 63) + dw;
                const bool v = ((unsigned)h2 < 64u) && ((unsigned)w2 < 64u);
                const size_t boff = (size_t)(v ? (h2 * 64 + w2) : 0) * 256 + k0 + c * 8;
                cp16(stb + so, B + boff, v);
            }
        }
        CP_COMMIT();
    };

    auto compute_stage = [&](int buf) {
        const uint32_t stb = sbase + buf * STAGE_BYTES;
        #pragma unroll
        for (int kh = 0; kh < 4; kh++) {
            uint32_t ah[4][4], bf[4][2];
            #pragma unroll
            for (int i = 0; i < 4; i++) {
                const int row = wm * 64 + i * 16 + (lane & 15);
                const int ch = (2 * kh + (lane >> 4)) ^ (row & 7);
                ldmat4(ah[i], stb + row * 128 + ch * 16);
            }
            #pragma unroll
            for (int jj = 0; jj < 2; jj++) {
                const int row = wn * 32 + jj * 16 + (lane & 7) + ((lane >> 4) << 3);
                const int ch = (2 * kh + ((lane >> 3) & 1)) ^ (row & 7);
                uint32_t r4[4];
                ldmat4(r4, stb + 16384 + row * 128 + ch * 16);
                bf[2*jj][0] = r4[0]; bf[2*jj][1] = r4[1];
                bf[2*jj+1][0] = r4[2]; bf[2*jj+1][1] = r4[3];
            }
            #pragma unroll
            for (int i = 0; i < 4; i++)
                #pragma unroll
                for (int j = 0; j < 4; j++)
                    mma16816(acc[i][j], ah[i], bf[j]);
        }
    };

    load_stage(0, 0);
    load_stage(1, 1);
    #pragma unroll 1
    for (int s = 0; s < 36; s++) {
        if (s + 1 < 36) { CP_WAIT1(); } else { CP_WAIT0(); }
        __syncthreads();
        if (s + 2 < 36) load_stage(s + 2, (s + 2) % 3);
        compute_stage(s % 3);
    }

    float* dst = out + (size_t)b * ND * NPIX;
    #pragma unroll
    for (int i = 0; i < 4; i++) {
        const int r0 = o0 + wm * 64 + i * 16 + (lane >> 2);
        const float sc0 = gamma[r0]     * rsqrtf(bn_var[r0]     + 1e-5f);
        const float sc1 = gamma[r0 + 8] * rsqrtf(bn_var[r0 + 8] + 1e-5f);
        const float ad0 = (b_out[r0]     - bn_mean[r0])     * sc0 + beta[r0];
        const float ad1 = (b_out[r0 + 8] - bn_mean[r0 + 8]) * sc1 + beta[r0 + 8];
        #pragma unroll
        for (int j = 0; j < 4; j++) {
            const int cb = n0 + wn * 32 + j * 8 + 2 * (lane & 3);
            float t0 = acc[i][j][0] * sc0 + ad0;
            float t1 = acc[i][j][1] * sc0 + ad0;
            float t2 = acc[i][j][2] * sc1 + ad1;
            float t3 = acc[i][j][3] * sc1 + ad1;
            float2 v0 = make_float2((t0 >= 0.f) ? t0 : 0.2f * t0,
                                    (t1 >= 0.f) ? t1 : 0.2f * t1);
            float2 v1 = make_float2((t2 >= 0.f) ? t2 : 0.2f * t2,
                                    (t3 >= 0.f) ? t3 : 0.2f * t3);
            *(float2*)(dst + (size_t)r0 * NPIX + cb) = v0;
            *(float2*)(dst + (size_t)(r0 + 8) * NPIX + cb) = v1;
        }
    }
}

// ---------------- attention middle (SIMT) ----------------
__global__ void __launch_bounds__(256) scores_partial_kernel()
{
    const int d = blockIdx.x;
    const int b = blockIdx.y;
    const int tid = threadIdx.x;
    __shared__ float Qs[64][65];
    __shared__ float Ks[64][65];
    const float* qb = g_q + ((size_t)b * ND + d) * NPIX;
    const float* kb = g_k + ((size_t)b * ND + d) * NPIX;

    for (int idx = tid; idx < 4096; idx += 256) {
        const int t = idx >> 6, l = idx & 63;
        const int off = ((t >> 3) * 8 + (l >> 3)) * 64 + (t & 7) * 8 + (l & 7);
        Qs[l][t] = qb[off];
        Ks[l][t] = kb[off];
    }
    __syncthreads();

    const int ty = tid >> 4, tx = tid & 15;
    float acc[4][4];
    #pragma unroll
    for (int i = 0; i < 4; i++)
        #pragma unroll
        for (int j = 0; j < 4; j++) acc[i][j] = 0.f;

    #pragma unroll 4
    for (int l = 0; l < 64; l++) {
        float qv[4], kv[4];
        #pragma unroll
        for (int i = 0; i < 4; i++) { qv[i] = Qs[l][ty + 16*i]; kv[i] = Ks[l][tx + 16*i]; }
        #pragma unroll
        for (int i = 0; i < 4; i++)
            #pragma unroll
            for (int j = 0; j < 4; j++) acc[i][j] += qv[i] * kv[j];
    }

    float* part = g_ao + ((size_t)b * ND + d) * NPIX;
    #pragma unroll
    for (int i = 0; i < 4; i++)
        #pragma unroll
        for (int j = 0; j < 4; j++)
            part[(ty + 16*i) * 64 + tx + 16*j] = acc[i][j];
}

__global__ void __launch_bounds__(256) scores_reduce_kernel()
{
    const int b  = blockIdx.y;
    const int tu = blockIdx.x * 256 + threadIdx.x;
    const float* pp = g_ao + (size_t)b * ND * NPIX + tu;
    float s = 0.f;
    #pragma unroll 8
    for (int d = 0; d < ND; d++) s += pp[(size_t)d * NPIX];
    g_scores[b * 4096 + tu] = s;
}

__global__ void __launch_bounds__(64) softmax_kernel()
{
    const int b = blockIdx.x;
    const int t = threadIdx.x;
    const float scale = 1.0f / 128.0f;
    const float* row = g_scores + b * 4096 + t * 64;
    float v[64];
    float m = -1e30f;
    #pragma unroll
    for (int u = 0; u < 64; u++) { v[u] = row[u] * scale; m = fmaxf(m, v[u]); }
    float s = 0.f;
    #pragma unroll
    for (int u = 0; u < 64; u++) { v[u] = __expf(v[u] - m); s += v[u]; }
    const float inv = 1.0f / s;
    float* arow = g_attn + b * 4096 + t * 64;
    #pragma unroll
    for (int u = 0; u < 64; u++) arow[u] = v[u] * inv;
}

__global__ void __launch_bounds__(256) av_kernel()
{
    const int h  = blockIdx.x;
    const int d0 = blockIdx.y * 16;
    const int b  = blockIdx.z;
    const int tid = threadIdx.x;

    __shared__ float attn_s[8][64];
    __shared__ float Vs[16][8][64];

    for (int idx = tid; idx < 512; idx += 256) {
        const int r = idx >> 6, j = idx & 63;
        attn_s[r][j] = g_attn[b * 4096 + ((h >> 3) * 8 + r) * 64 + j];
    }
    for (int idx = tid; idx < 8192; idx += 256) {
        const int dl = idx >> 9, j2 = (idx >> 6) & 7, w = idx & 63;
        Vs[dl][j2][w] = g_v[(((size_t)b * ND + d0 + dl) * 64 + j2 * 8 + (h & 7)) * 64 + w];
    }
    __syncthreads();

    const int dg = (tid >> 6) * 4;
    const int w  = tid & 63;
    float acc[4] = {0.f, 0.f, 0.f, 0.f};
    #pragma unroll 8
    for (int j = 0; j < 64; j++) {
        const float a = attn_s[w >> 3][j];
        const int col = ((j & 7) << 3) | (w & 7);
        #pragma unroll
        for (int q = 0; q < 4; q++) acc[q] += a * Vs[dg + q][j >> 3][col];
    }
    #pragma unroll
    for (int q = 0; q < 4; q++)
        g_ao[(((size_t)b * ND + d0 + dg + q) * 64 + h) * 64 + w] = acc[q];
}

// ---------------- host ----------------
extern "C" void kernel_launch(void* const* d_in, const int* in_sizes, int n_in,
                              void* d_out, int out_size)
{
    const float* x       = (const float*)d_in[0];
    const float* wq      = (const float*)d_in[1];
    const float* bq      = (const float*)d_in[2];
    const float* wk      = (const float*)d_in[3];
    const float* bk      = (const float*)d_in[4];
    const float* wv      = (const float*)d_in[5];
    const float* bv      = (const float*)d_in[6];
    const float* w_out   = (const float*)d_in[7];
    const float* b_out   = (const float*)d_in[8];
    const float* gamma   = (const float*)d_in[9];
    const float* beta    = (const float*)d_in[10];
    const float* bn_mean = (const float*)d_in[11];
    const float* bn_var  = (const float*)d_in[12];
    float* out = (float*)d_out;

    cudaFuncSetAttribute(qkv_mma_kernel,  cudaFuncAttributeMaxDynamicSharedMemorySize, SMEM_BYTES);
    cudaFuncSetAttribute(conv_mma_kernel, cudaFuncAttributeMaxDynamicSharedMemorySize, SMEM_BYTES);

    convert_wqkv_kernel <<<768,  256>>>(wq, wk, wv);
    convert_wconv_kernel<<<2304, 256>>>(w_out);
    convert_transpose_kernel<0><<<dim3(128, 8, 16), 256>>>(x);

    qkv_mma_kernel<<<dim3(32, 2, 48), 256, SMEM_BYTES>>>(bq, bk, bv);

    scores_partial_kernel<<<dim3(256, 16), 256>>>();
    scores_reduce_kernel <<<dim3(16, 16), 256>>>();
    softmax_kernel<<<16, 64>>>();
    av_kernel<<<dim3(64, 16, 16), 256>>>();

    convert_transpose_kernel<1><<<dim3(128, 8, 16), 256>>>(nullptr);
    conv_mma_kernel<<<dim3(32, 2, 16), 256, SMEM_BYTES>>>(b_out, gamma, beta, bn_mean, bn_var, out);
}